// round 3
// baseline (speedup 1.0000x reference)
#include <cuda_runtime.h>

#define SEQ_LEN    2048
#define STATE_LEN  1024
#define N_POI      10000
#define EPS_VAL    1e-6f
#define THREADS    256
#define PER_T      (SEQ_LEN / THREADS)   // 8
#define SORT_T     1024
#define BINS_PER_T 10                    // ceil(10000/1024)

// sorted (key << 11 | orig_pos), ascending by key
__device__ unsigned int g_packed[SEQ_LEN];

// ---------------- Kernel A: counting sort of his (1 CTA) ----------------
__global__ __launch_bounds__(SORT_T)
void sort_his_kernel(const int* __restrict__ his)
{
    __shared__ int cnt[N_POI];        // 40000 B
    __shared__ int sscan[SORT_T];
    const int tid = threadIdx.x;

    // zero histogram
    for (int i = tid; i < N_POI; i += SORT_T) cnt[i] = 0;
    __syncthreads();

    // histogram
    for (int j = tid; j < SEQ_LEN; j += SORT_T)
        atomicAdd(&cnt[__ldg(his + j)], 1);
    __syncthreads();

    // per-thread serial sum over its 10 bins
    const int base = tid * BINS_PER_T;
    int S = 0;
    if (base < N_POI) {
        const int nb = min(BINS_PER_T, N_POI - base);
        for (int b = 0; b < nb; b++) S += cnt[base + b];
    }

    // Hillis-Steele inclusive scan over 1024 partials
    sscan[tid] = S;
    __syncthreads();
    for (int d = 1; d < SORT_T; d <<= 1) {
        int t = (tid >= d) ? sscan[tid - d] : 0;
        __syncthreads();
        sscan[tid] += t;
        __syncthreads();
    }
    int run = sscan[tid] - S;   // exclusive offset for this thread's bins

    // write back exclusive offsets into cnt
    if (base < N_POI) {
        const int nb = min(BINS_PER_T, N_POI - base);
        for (int b = 0; b < nb; b++) {
            const int c = cnt[base + b];
            cnt[base + b] = run;
            run += c;
        }
    }
    __syncthreads();

    // scatter packed (key<<11 | pos). Tie order among equal keys is
    // atomic-dependent but value-equivalent (equal keys -> equal values).
    for (int j = tid; j < SEQ_LEN; j += SORT_T) {
        const int key = __ldg(his + j);
        const int idx = atomicAdd(&cnt[key], 1);
        g_packed[idx] = ((unsigned)key << 11) | (unsigned)j;
    }
}

// ---------------- Kernel B: sorted gather + softmax ----------------
__global__ __launch_bounds__(THREADS)
void attn_loc_kernel(const int* __restrict__ cur,
                     const float* __restrict__ mat,
                     float* __restrict__ out)
{
    __shared__ float sval[SEQ_LEN];   // energies at original positions (8KB)
    __shared__ float sred[THREADS / 32];

    const int row = blockIdx.x;
    const int tid = threadIdx.x;

    const float* __restrict__ mrow = mat + (size_t)__ldg(cur + row) * N_POI;

    // Phase 1: gather in sorted-key order (warp spans ~6 cache lines)
    float v[PER_T];
    int   pos[PER_T];
    float mx = -INFINITY;
#pragma unroll
    for (int k = 0; k < PER_T; k++) {
        const unsigned pk = g_packed[tid + k * THREADS];
        const int key = (int)(pk >> 11);
        pos[k] = (int)(pk & 2047u);
        const float d = __ldg(mrow + key);
        const float e = (d != 0.0f) ? (1.0f / d) : EPS_VAL;
        v[k] = e;
        mx = fmaxf(mx, e);
    }

    // block max
#pragma unroll
    for (int o = 16; o; o >>= 1)
        mx = fmaxf(mx, __shfl_xor_sync(0xffffffffu, mx, o));
    if ((tid & 31) == 0) sred[tid >> 5] = mx;
    __syncthreads();
    float bmax = sred[0];
#pragma unroll
    for (int w = 1; w < THREADS / 32; w++) bmax = fmaxf(bmax, sred[w]);
    __syncthreads();

    // Phase 2: exp, local sum, scatter to original position in smem
    float sum = 0.0f;
#pragma unroll
    for (int k = 0; k < PER_T; k++) {
        const float e = __expf(v[k] - bmax);
        sum += e;
        sval[pos[k]] = e;
    }

    // block sum
#pragma unroll
    for (int o = 16; o; o >>= 1)
        sum += __shfl_xor_sync(0xffffffffu, sum, o);
    if ((tid & 31) == 0) sred[tid >> 5] = sum;
    __syncthreads();   // also makes sval scatter visible
    float bsum = 0.0f;
#pragma unroll
    for (int w = 0; w < THREADS / 32; w++) bsum += sred[w];

    // Phase 3: normalize + coalesced float4 store
    const float inv = 1.0f / bsum;
    float4* __restrict__ orow4 = (float4*)(out + (size_t)row * SEQ_LEN);
    const float4* __restrict__ sval4 = (const float4*)sval;
#pragma unroll
    for (int k = 0; k < SEQ_LEN / 4 / THREADS; k++) {   // 2 iters
        float4 t = sval4[tid + k * THREADS];
        t.x *= inv; t.y *= inv; t.z *= inv; t.w *= inv;
        orow4[tid + k * THREADS] = t;
    }
}

extern "C" void kernel_launch(void* const* d_in, const int* in_sizes, int n_in,
                              void* d_out, int out_size)
{
    const int*   his = (const int*)d_in[0];
    const int*   cur = (const int*)d_in[1];
    const float* mat = (const float*)d_in[2];
    float*       out = (float*)d_out;

    sort_his_kernel<<<1, SORT_T>>>(his);
    attn_loc_kernel<<<STATE_LEN, THREADS>>>(cur, mat, out);
}

// round 4
// speedup vs baseline: 1.9818x; 1.9818x over previous
#include <cuda_runtime.h>
#include <cstdint>

#define SEQ_LEN   2048
#define STATE_LEN 1024
#define N_POI     10000
#define ROW_BYTES (N_POI * 4)            // 40000, multiple of 16
#define EPS_VAL   1e-6f
#define THREADS   256
#define PER_T     (SEQ_LEN / THREADS)    // 8

__global__ __launch_bounds__(THREADS)
void attn_loc_kernel(const int* __restrict__ his,
                     const int* __restrict__ cur,
                     const float* __restrict__ mat,
                     float* __restrict__ out)
{
    __shared__ alignas(128) float srow[N_POI];   // 40000 B row buffer
    __shared__ float sred[THREADS / 32];
    __shared__ alignas(8) uint64_t mbar;

    const int row = blockIdx.x;
    const int tid = threadIdx.x;

    const uint32_t mbar_addr = (uint32_t)__cvta_generic_to_shared(&mbar);

    if (tid == 0) {
        asm volatile("mbarrier.init.shared.b64 [%0], %1;"
                     :: "r"(mbar_addr), "r"(1) : "memory");
    }
    __syncthreads();

    // One thread kicks off the TMA bulk copy of the whole row (40KB in flight
    // per CTA -> DRAM latency fully covered without register MLP limits).
    if (tid == 0) {
        asm volatile("mbarrier.arrive.expect_tx.shared.b64 _, [%0], %1;"
                     :: "r"(mbar_addr), "r"((uint32_t)ROW_BYTES) : "memory");
        const uint32_t dst = (uint32_t)__cvta_generic_to_shared(srow);
        const char* src = (const char*)mat + (size_t)__ldg(cur + row) * ROW_BYTES;
        asm volatile(
            "cp.async.bulk.shared::cluster.global.mbarrier::complete_tx::bytes "
            "[%0], [%1], %2, [%3];"
            :: "r"(dst), "l"(src), "r"((uint32_t)ROW_BYTES), "r"(mbar_addr)
            : "memory");
    }

    // Overlap the TMA with the index prefetch (his is L2-resident, 8KB).
    int cidx[PER_T];
#pragma unroll
    for (int k = 0; k < PER_T; k++)
        cidx[k] = __ldg(his + tid + k * THREADS);

    // Wait for the row to land (acquire orders the subsequent ld.shared).
    {
        uint32_t done;
        asm volatile(
            "{\n\t"
            ".reg .pred p;\n\t"
            "mbarrier.try_wait.parity.acquire.cta.shared::cta.b64 p, [%1], %2;\n\t"
            "selp.b32 %0, 1, 0, p;\n\t"
            "}"
            : "=r"(done) : "r"(mbar_addr), "r"(0u) : "memory");
        if (!done) {
            asm volatile(
                "{\n\t"
                ".reg .pred P1;\n\t"
                "W_%=:\n\t"
                "mbarrier.try_wait.parity.acquire.cta.shared::cta.b64 P1, [%0], %1, 0x989680;\n\t"
                "@P1 bra.uni D_%=;\n\t"
                "bra.uni W_%=;\n\t"
                "D_%=:\n\t"
                "}"
                :: "r"(mbar_addr), "r"(0u) : "memory");
        }
    }

    // Phase 1: gather from smem (random LDS, conflict deg ~3 -> cheap)
    float v[PER_T];
    float mx = -INFINITY;
#pragma unroll
    for (int k = 0; k < PER_T; k++) {
        const float d = srow[cidx[k]];
        const float e = (d != 0.0f) ? (1.0f / d) : EPS_VAL;
        v[k] = e;
        mx = fmaxf(mx, e);
    }

    // Block max reduction
#pragma unroll
    for (int o = 16; o; o >>= 1)
        mx = fmaxf(mx, __shfl_xor_sync(0xffffffffu, mx, o));
    if ((tid & 31) == 0) sred[tid >> 5] = mx;
    __syncthreads();
    float bmax = sred[0];
#pragma unroll
    for (int w = 1; w < THREADS / 32; w++) bmax = fmaxf(bmax, sred[w]);
    __syncthreads();

    // Phase 2: exp + local sum
    float sum = 0.0f;
#pragma unroll
    for (int k = 0; k < PER_T; k++) {
        const float e = __expf(v[k] - bmax);
        v[k] = e;
        sum += e;
    }

    // Block sum reduction
#pragma unroll
    for (int o = 16; o; o >>= 1)
        sum += __shfl_xor_sync(0xffffffffu, sum, o);
    if ((tid & 31) == 0) sred[tid >> 5] = sum;
    __syncthreads();
    float bsum = 0.0f;
#pragma unroll
    for (int w = 0; w < THREADS / 32; w++) bsum += sred[w];

    // Phase 3: normalize + coalesced store
    const float inv = 1.0f / bsum;
    float* __restrict__ orow = out + (size_t)row * SEQ_LEN;
#pragma unroll
    for (int k = 0; k < PER_T; k++)
        orow[tid + k * THREADS] = v[k] * inv;
}

extern "C" void kernel_launch(void* const* d_in, const int* in_sizes, int n_in,
                              void* d_out, int out_size)
{
    const int*   his = (const int*)d_in[0];
    const int*   cur = (const int*)d_in[1];
    const float* mat = (const float*)d_in[2];
    float*       out = (float*)d_out;

    attn_loc_kernel<<<STATE_LEN, THREADS>>>(his, cur, mat, out);
}